// round 14
// baseline (speedup 1.0000x reference)
#include <cuda_runtime.h>
#include <cuda_bf16.h>
#include <cuda_fp16.h>
#include <cstdint>

#define BB   512
#define SEQL 512
#define IND  128
#define HID  256
#define TT   24
#define TEMP 64
#define NHU  128    // hU blocks prepended to attn grid

// ---------------- persistent device scratch (no allocations) ----------------
__device__ __nv_bfloat16 g_H16[(size_t)BB * SEQL * IND];   // 67 MB
__device__ __nv_bfloat16 g_Wa16[IND * TT * TEMP];          // 384 KB
__device__ float g_h[BB * HID];
__device__ float g_c[BB * HID];
__device__ float g_y[BB];
__device__ float g_cua[BB * TEMP];
__device__ float g_ctxp[BB * 4 * IND];                     // 4 ctx partials per batch
__device__ float g_psum[BB * 4];
__device__ float g_ctx[BB * IND];
__device__ float g_hU[BB * 4 * HID];                       // h@U + bias + y*Wy
__device__ float g_gates[BB * 4 * HID];

// ---------------- asm helpers ----------------
__device__ __forceinline__ void ldsm4(uint32_t* r, uint32_t a) {
    asm volatile("ldmatrix.sync.aligned.m8n8.x4.shared.b16 {%0,%1,%2,%3}, [%4];\n"
        : "=r"(r[0]), "=r"(r[1]), "=r"(r[2]), "=r"(r[3]) : "r"(a));
}
__device__ __forceinline__ void ldsm4t(uint32_t* r, uint32_t a) {
    asm volatile("ldmatrix.sync.aligned.m8n8.x4.trans.shared.b16 {%0,%1,%2,%3}, [%4];\n"
        : "=r"(r[0]), "=r"(r[1]), "=r"(r[2]), "=r"(r[3]) : "r"(a));
}
__device__ __forceinline__ void mma_bf16(float* d, const uint32_t* a, const uint32_t* b) {
    asm volatile("mma.sync.aligned.m16n8k16.row.col.f32.bf16.bf16.f32 "
        "{%0,%1,%2,%3}, {%4,%5,%6,%7}, {%8,%9}, {%0,%1,%2,%3};\n"
        : "+f"(d[0]), "+f"(d[1]), "+f"(d[2]), "+f"(d[3])
        : "r"(a[0]), "r"(a[1]), "r"(a[2]), "r"(a[3]), "r"(b[0]), "r"(b[1]));
}
__device__ __forceinline__ void mma_tf32(float* d, const uint32_t* a, uint32_t b0, uint32_t b1) {
    asm volatile("mma.sync.aligned.m16n8k8.row.col.f32.tf32.tf32.f32 "
        "{%0,%1,%2,%3}, {%4,%5,%6,%7}, {%8,%9}, {%0,%1,%2,%3};\n"
        : "+f"(d[0]), "+f"(d[1]), "+f"(d[2]), "+f"(d[3])
        : "r"(a[0]), "r"(a[1]), "r"(a[2]), "r"(a[3]), "r"(b0), "r"(b1));
}
__device__ __forceinline__ uint32_t f2tf32(float v) {
    uint32_t u; asm("cvt.rna.tf32.f32 %0, %1;" : "=r"(u) : "f"(v)); return u;
}
__device__ __forceinline__ float2 tanh2(float x0, float x1) {
    uint32_t r;
    asm("{\n\t.reg .b32 p;\n\tcvt.rn.f16x2.f32 p, %1, %2;\n\ttanh.approx.f16x2 %0, p;\n\t}"
        : "=r"(r) : "f"(x1), "f"(x0));
    __half2 h = *reinterpret_cast<__half2*>(&r);
    return __half22float2(h);
}
__device__ __forceinline__ void cp_async16(uint32_t dst, const void* src) {
    asm volatile("cp.async.cg.shared.global [%0], [%1], 16;\n" :: "r"(dst), "l"(src));
}
__device__ __forceinline__ void cp_commit() {
    asm volatile("cp.async.commit_group;\n" ::: "memory");
}
template<int N> __device__ __forceinline__ void cp_wait() {
    asm volatile("cp.async.wait_group %0;\n" :: "n"(N) : "memory");
}
__device__ __forceinline__ uint32_t pack_bf16x2(float a, float b) {
    __nv_bfloat162 p = __floats2bfloat162_rn(a, b);
    return *(const uint32_t*)&p;
}

// ---------------- converts ----------------
__global__ void convert_H(const float* __restrict__ H) {
    int i = blockIdx.x * blockDim.x + threadIdx.x;
    float4 v = ((const float4*)H)[i];
    uint2 o;
    o.x = pack_bf16x2(v.x, v.y);
    o.y = pack_bf16x2(v.z, v.w);
    ((uint2*)g_H16)[i] = o;
}
__global__ void convert_Wa(const float* __restrict__ Wa) {
    int i = blockIdx.x * blockDim.x + threadIdx.x;
    float4 v = ((const float4*)Wa)[i];
    uint2 o;
    o.x = pack_bf16x2(v.x, v.y);
    o.y = pack_bf16x2(v.z, v.w);
    ((uint2*)g_Wa16)[i] = o;
}

// ---------------- init: state + cUa(t=0) ----------------
__global__ void init_state(const float* __restrict__ emb, const float* __restrict__ y0,
                           const float* __restrict__ Ua) {
    __shared__ float sc[256];
    __shared__ float sp[256];
    int b = blockIdx.x, j = threadIdx.x;
    float h = emb[b * 2 * HID + j];
    float c = emb[b * 2 * HID + HID + j];
    g_h[b * HID + j] = h;
    g_c[b * HID + j] = c;
    sc[j] = c;
    if (j == 0) g_y[b] = y0[b];
    __syncthreads();
    int k = j & 63, part = j >> 6;
    const float* Uc = Ua + k;
    float a = 0.f;
    int j0 = part * 64;
    #pragma unroll 8
    for (int jj = j0; jj < j0 + 64; jj++) a += sc[jj] * Uc[(size_t)jj * (TT * 64)];
    sp[part * 64 + k] = a;
    __syncthreads();
    if (j < 64) g_cua[b * 64 + j] = sp[j] + sp[64 + j] + sp[128 + j] + sp[192 + j];
}

// ---------------- merged kernel: hU blocks (0..127) + attn blocks (128..2175) ----------------
#define AH_STRIDE 136
#define AW_STRIDE 72
#define ATTN2_SMEM (128 * AH_STRIDE * 2 + IND * AW_STRIDE * 2 + 64 * 8 + 128 * 4)

__global__ __launch_bounds__(256, 4) void attn_hu(
    const float* __restrict__ ba, const float* __restrict__ Va,
    const float* __restrict__ U, const float* __restrict__ bias,
    const float* __restrict__ Wy, int t)
{
    extern __shared__ char smraw[];
    int tid = threadIdx.x, warp = tid >> 5, lane = tid & 31;

    if (blockIdx.x < NHU) {
        // ------- hU path: g_hU = h @ U_t + bias + y*Wy, tile 64b x 64n, k=256 -------
        float (*As)[64][36] = (float (*)[64][36])smraw;
        float (*Bs)[32][72] = (float (*)[32][72])(smraw + 2 * 64 * 36 * 4);
        int wm = warp & 3, wn = warp >> 2;
        int n0 = (blockIdx.x & 15) * 64, b0 = (blockIdx.x >> 4) * 64;
        float acc[4][4] = {};

        auto copy_chunk = [&](int kc, int buf) {
            #pragma unroll
            for (int i = tid; i < 512; i += 256) {
                int row = i >> 3, seg = i & 7;
                const float* src = g_h + (size_t)(b0 + row) * HID + kc * 32 + seg * 4;
                cp_async16((uint32_t)__cvta_generic_to_shared(&As[buf][row][seg * 4]), src);
            }
            #pragma unroll
            for (int i = tid; i < 512; i += 256) {
                int k = i >> 4, seg = i & 15;
                const float* src = U + (size_t)(kc * 32 + k) * (TT * 1024) + (size_t)t * 1024 + n0 + seg * 4;
                cp_async16((uint32_t)__cvta_generic_to_shared(&Bs[buf][k][seg * 4]), src);
            }
        };

        copy_chunk(0, 0); cp_commit();
        copy_chunk(1, 1); cp_commit();

        for (int kc = 0; kc < 8; kc++) {
            cp_wait<1>();
            __syncthreads();
            int buf = kc & 1;
            int ar = wm * 16 + (lane >> 2);
            int bk = lane & 3;
            int bn = wn * 32 + (lane >> 2);
            #pragma unroll
            for (int ks = 0; ks < 4; ks++) {
                uint32_t a[4];
                int ac = ks * 8 + (lane & 3);
                a[0] = f2tf32(As[buf][ar][ac]);
                a[1] = f2tf32(As[buf][ar + 8][ac]);
                a[2] = f2tf32(As[buf][ar][ac + 4]);
                a[3] = f2tf32(As[buf][ar + 8][ac + 4]);
                #pragma unroll
                for (int nt = 0; nt < 4; nt++) {
                    uint32_t b0r = f2tf32(Bs[buf][ks * 8 + bk][bn + nt * 8]);
                    uint32_t b1r = f2tf32(Bs[buf][ks * 8 + bk + 4][bn + nt * 8]);
                    mma_tf32(acc[nt], a, b0r, b1r);
                }
            }
            __syncthreads();
            if (kc + 2 < 8) copy_chunk(kc + 2, buf);
            cp_commit();
        }

        int r0 = b0 + wm * 16 + (lane >> 2);
        float y0v = g_y[r0], y1v = g_y[r0 + 8];
        #pragma unroll
        for (int nt = 0; nt < 4; nt++) {
            int n = n0 + wn * 32 + nt * 8 + (lane & 3) * 2;
            float bb0 = bias[t * 1024 + n],   bb1 = bias[t * 1024 + n + 1];
            float wy0 = Wy[t * 1024 + n],     wy1 = Wy[t * 1024 + n + 1];
            g_hU[(size_t)r0 * 1024 + n]           = acc[nt][0] + bb0 + y0v * wy0;
            g_hU[(size_t)r0 * 1024 + n + 1]       = acc[nt][1] + bb1 + y0v * wy1;
            g_hU[(size_t)(r0 + 8) * 1024 + n]     = acc[nt][2] + bb0 + y1v * wy0;
            g_hU[(size_t)(r0 + 8) * 1024 + n + 1] = acc[nt][3] + bb1 + y1v * wy1;
        }
        return;
    }

    // ------- attn path -------
    __nv_bfloat16* sA = (__nv_bfloat16*)smraw;
    __nv_bfloat16* sW = sA + 128 * AH_STRIDE;
    float* sctxp = (float*)sW;
    float2* sVC = (float2*)(smraw + 128 * AH_STRIDE * 2 + IND * AW_STRIDE * 2);
    float* se = (float*)(sVC + 64);

    int abid = blockIdx.x - NHU;
    int m0 = abid * 128;
    int b = m0 >> 9;
    int blkInB = abid & 3;
    uint32_t aBase = (uint32_t)__cvta_generic_to_shared(sA);
    uint32_t wBase = (uint32_t)__cvta_generic_to_shared(sW);

    #pragma unroll
    for (int i = tid; i < 1024; i += 256) {
        int row = i >> 3, seg = i & 7;
        cp_async16(aBase + (uint32_t)(row * AH_STRIDE + seg * 8) * 2,
                   g_H16 + (size_t)(m0 + row) * IND + seg * 8);
    }
    #pragma unroll
    for (int i = tid; i < 512; i += 256) {
        int row = i >> 3, seg = i & 7;
        cp_async16(wBase + (uint32_t)(row * AW_STRIDE + seg * 8) * 2,
                   g_Wa16 + (size_t)row * (TT * TEMP) + t * TEMP + seg * 8);
    }
    cp_commit();
    #pragma unroll
    for (int i = tid; i < 1024; i += 256) {
        int row = i >> 3, seg = (i & 7) + 8;
        cp_async16(aBase + (uint32_t)(row * AH_STRIDE + seg * 8) * 2,
                   g_H16 + (size_t)(m0 + row) * IND + seg * 8);
    }
    #pragma unroll
    for (int i = tid; i < 512; i += 256) {
        int row = (i >> 3) + 64, seg = i & 7;
        cp_async16(wBase + (uint32_t)(row * AW_STRIDE + seg * 8) * 2,
                   g_Wa16 + (size_t)row * (TT * TEMP) + t * TEMP + seg * 8);
    }
    cp_commit();

    if (tid < 64) {
        float cb = ba[t * 64 + tid] + g_cua[b * 64 + tid];
        sVC[tid] = make_float2(Va[tid * TT + t], cb);
    }

    float acc[8][4];
    #pragma unroll
    for (int ni = 0; ni < 8; ni++)
        #pragma unroll
        for (int r = 0; r < 4; r++) acc[ni][r] = 0.f;

    int lr = lane & 7, lg = (lane >> 3) & 1, lc = lane >> 4;
    int R = warp * 16;

    cp_wait<1>();
    __syncthreads();
    #pragma unroll
    for (int ks = 0; ks < 4; ks++) {
        uint32_t afr[4];
        ldsm4(afr, aBase + (uint32_t)((R + lr + lg * 8) * AH_STRIDE + ks * 16 + lc * 8) * 2);
        uint32_t bfr[4][4];
        #pragma unroll
        for (int p = 0; p < 4; p++) {
            int row = ks * 16 + lr + lg * 8;
            int col = p * 16 + lc * 8;
            ldsm4t(bfr[p], wBase + (uint32_t)(row * AW_STRIDE + col) * 2);
        }
        #pragma unroll
        for (int p = 0; p < 4; p++) {
            mma_bf16(acc[2 * p],     afr, &bfr[p][0]);
            mma_bf16(acc[2 * p + 1], afr, &bfr[p][2]);
        }
    }
    cp_wait<0>();
    __syncthreads();
    #pragma unroll
    for (int ks = 4; ks < 8; ks++) {
        uint32_t afr[4];
        ldsm4(afr, aBase + (uint32_t)((R + lr + lg * 8) * AH_STRIDE + ks * 16 + lc * 8) * 2);
        uint32_t bfr[4][4];
        #pragma unroll
        for (int p = 0; p < 4; p++) {
            int row = ks * 16 + lr + lg * 8;
            int col = p * 16 + lc * 8;
            ldsm4t(bfr[p], wBase + (uint32_t)(row * AW_STRIDE + col) * 2);
        }
        #pragma unroll
        for (int p = 0; p < 4; p++) {
            mma_bf16(acc[2 * p],     afr, &bfr[p][0]);
            mma_bf16(acc[2 * p + 1], afr, &bfr[p][2]);
        }
    }

    {
        int q = lane & 3, r = lane >> 2;
        float s0 = 0.f, s1 = 0.f;
        #pragma unroll
        for (int ni = 0; ni < 8; ni++) {
            int k0 = ni * 8 + q * 2;
            float2 vc0 = sVC[k0], vc1 = sVC[k0 + 1];
            float2 t0 = tanh2(acc[ni][0] + vc0.y, acc[ni][1] + vc1.y);
            s0 += vc0.x * t0.x + vc1.x * t0.y;
            float2 t1 = tanh2(acc[ni][2] + vc0.y, acc[ni][3] + vc1.y);
            s1 += vc0.x * t1.x + vc1.x * t1.y;
        }
        s0 += __shfl_xor_sync(0xffffffffu, s0, 1);
        s0 += __shfl_xor_sync(0xffffffffu, s0, 2);
        s1 += __shfl_xor_sync(0xffffffffu, s1, 1);
        s1 += __shfl_xor_sync(0xffffffffu, s1, 2);
        if (q == 0) {
            se[R + r]     = __expf(s0 * 0.0625f);
            se[R + r + 8] = __expf(s1 * 0.0625f);
        }
    }
    __syncthreads();

    if (tid < 32) {
        float p = se[tid] + se[tid + 32] + se[tid + 64] + se[tid + 96];
        #pragma unroll
        for (int off = 16; off; off >>= 1) p += __shfl_xor_sync(0xffffffffu, p, off);
        if (tid == 0) g_psum[b * 4 + blkInB] = p;
    }

    {
        int q = tid & 15, part = tid >> 4;
        float a[8] = {0.f, 0.f, 0.f, 0.f, 0.f, 0.f, 0.f, 0.f};
        #pragma unroll
        for (int r = 0; r < 8; r++) {
            int row = part * 8 + r;
            float pl = se[row];
            uint4 v = *(const uint4*)(sA + row * AH_STRIDE + q * 8);
            const __nv_bfloat162* h2 = (const __nv_bfloat162*)&v;
            #pragma unroll
            for (int i = 0; i < 4; i++) {
                float2 f = __bfloat1622float2(h2[i]);
                a[2 * i]     += pl * f.x;
                a[2 * i + 1] += pl * f.y;
            }
        }
        #pragma unroll
        for (int i = 0; i < 8; i++) sctxp[part * 128 + q * 8 + i] = a[i];
        __syncthreads();
        if (tid < 128) {
            float sum = 0.f;
            #pragma unroll
            for (int p = 0; p < 16; p++) sum += sctxp[p * 128 + tid];
            g_ctxp[(size_t)(b * 4 + blkInB) * IND + tid] = sum;
        }
    }
}

// ---------------- normalize: ctx = (sum of 4 ctx partials) / (sum of 4 psums) ----------------
__global__ void normalize_ctx() {
    __shared__ float sinv;
    int b = blockIdx.x, d = threadIdx.x;   // 128 threads
    if (d == 0) {
        sinv = 1.f / (g_psum[b * 4] + g_psum[b * 4 + 1] + g_psum[b * 4 + 2] + g_psum[b * 4 + 3]);
    }
    __syncthreads();
    const float* cp = g_ctxp + (size_t)b * 4 * IND;
    g_ctx[b * IND + d] = (cp[d] + cp[IND + d] + cp[2 * IND + d] + cp[3 * IND + d]) * sinv;
}

// ---------------- gates: ctx@W (k=128) + g_hU ----------------
__global__ __launch_bounds__(256) void gates_kernel(
    const float* __restrict__ W, int t)
{
    __shared__ float As[2][64][36];
    __shared__ float Bs[2][32][40];
    int tid = threadIdx.x;
    int warp = tid >> 5, lane = tid & 31;
    int wm = warp & 3, wn = warp >> 2;
    int n0 = blockIdx.x * 32, b0 = blockIdx.y * 64;
    float acc[2][4] = {};

    auto copy_chunk = [&](int kc, int buf) {
        #pragma unroll
        for (int i = tid; i < 512; i += 256) {
            int row = i >> 3, seg = i & 7;
            const float* src = g_ctx + (size_t)(b0 + row) * IND + kc * 32 + seg * 4;
            cp_async16((uint32_t)__cvta_generic_to_shared(&As[buf][row][seg * 4]), src);
        }
        {
            int k = tid >> 3, seg = tid & 7;
            const float* src = W + (size_t)(kc * 32 + k) * (TT * 1024) + (size_t)t * 1024 + n0 + seg * 4;
            cp_async16((uint32_t)__cvta_generic_to_shared(&Bs[buf][k][seg * 4]), src);
        }
    };

    copy_chunk(0, 0); cp_commit();
    copy_chunk(1, 1); cp_commit();

    for (int kc = 0; kc < 4; kc++) {
        cp_wait<1>();
        __syncthreads();
        int buf = kc & 1;
        int ar = wm * 16 + (lane >> 2);
        int bk = lane & 3;
        int bn = wn * 16 + (lane >> 2);
        #pragma unroll
        for (int ks = 0; ks < 4; ks++) {
            uint32_t a[4];
            int ac = ks * 8 + (lane & 3);
            a[0] = f2tf32(As[buf][ar][ac]);
            a[1] = f2tf32(As[buf][ar + 8][ac]);
            a[2] = f2tf32(As[buf][ar][ac + 4]);
            a[3] = f2tf32(As[buf][ar + 8][ac + 4]);
            #pragma unroll
            for (int nt = 0; nt < 2; nt++) {
                uint32_t b0r = f2tf32(Bs[buf][ks * 8 + bk][bn + nt * 8]);
                uint32_t b1r = f2tf32(Bs[buf][ks * 8 + bk + 4][bn + nt * 8]);
                mma_tf32(acc[nt], a, b0r, b1r);
            }
        }
        __syncthreads();
        if (kc + 2 < 4) copy_chunk(kc + 2, buf);
        cp_commit();
    }

    int r0 = b0 + wm * 16 + (lane >> 2);
    #pragma unroll
    for (int nt = 0; nt < 2; nt++) {
        int n = n0 + wn * 16 + nt * 8 + (lane & 3) * 2;
        g_gates[(size_t)r0 * 1024 + n]           = acc[nt][0] + g_hU[(size_t)r0 * 1024 + n];
        g_gates[(size_t)r0 * 1024 + n + 1]       = acc[nt][1] + g_hU[(size_t)r0 * 1024 + n + 1];
        g_gates[(size_t)(r0 + 8) * 1024 + n]     = acc[nt][2] + g_hU[(size_t)(r0 + 8) * 1024 + n];
        g_gates[(size_t)(r0 + 8) * 1024 + n + 1] = acc[nt][3] + g_hU[(size_t)(r0 + 8) * 1024 + n + 1];
    }
}

// ---------------- update: 64 blocks x 8 batches — Ua reused in registers ----------------
__global__ __launch_bounds__(256) void update_kernel(
    const float* __restrict__ fcw, const float* __restrict__ fcb,
    const float* __restrict__ Ua, int t,
    float* __restrict__ outy, float* __restrict__ outh)
{
    __shared__ float sc[8][256];
    __shared__ float red[8][8];
    __shared__ float sp2[4][8][64];
    int b0 = blockIdx.x * 8, j = threadIdx.x;
    int lane = j & 31, w = j >> 5;

    #pragma unroll
    for (int bi = 0; bi < 8; bi++) {
        int b = b0 + bi;
        size_t gi = (size_t)b * 1024;
        float i_ = 1.f / (1.f + __expf(-g_gates[gi + j]));
        float f_ = 1.f / (1.f + __expf(-g_gates[gi + 256 + j]));
        float gv = tanhf(g_gates[gi + 512 + j]);
        float o_ = 1.f / (1.f + __expf(-g_gates[gi + 768 + j]));
        float c = f_ * g_c[b * HID + j] + i_ * gv;
        float h = o_ * tanhf(c);
        g_c[b * HID + j] = c;
        g_h[b * HID + j] = h;
        sc[bi][j] = c;
        outh[(size_t)b * TT * HID + (size_t)t * HID + j] = h;

        float p = h * fcw[t * HID + j];
        #pragma unroll
        for (int off = 16; off; off >>= 1) p += __shfl_xor_sync(0xffffffffu, p, off);
        if (lane == 0) red[bi][w] = p;
    }
    __syncthreads();
    if (j < 8) {
        float s = red[j][0] + red[j][1] + red[j][2] + red[j][3] +
                  red[j][4] + red[j][5] + red[j][6] + red[j][7] + fcb[t];
        g_y[b0 + j] = s;
        outy[(b0 + j) * TT + t] = s;
    }

    // cUa for step t+1: Ua value loaded once, reused across 8 batches
    if (t + 1 < TT) {
        int k = j & 63, part = j >> 6;
        const float* Uc = Ua + (size_t)(t + 1) * 64 + k;
        float acc[8] = {0.f, 0.f, 0.f, 0.f, 0.f, 0.f, 0.f, 0.f};
        int j0 = part * 64;
        #pragma unroll 4
        for (int jj = j0; jj < j0 + 64; jj++) {
            float u = Uc[(size_t)jj * (TT * 64)];
            #pragma unroll
            for (int bi = 0; bi < 8; bi++) acc[bi] += sc[bi][jj] * u;
        }
        #pragma unroll
        for (int bi = 0; bi < 8; bi++) sp2[part][bi][k] = acc[bi];
        __syncthreads();
        // 512 (bi,k) results, 256 threads -> 2 each
        #pragma unroll
        for (int r = 0; r < 2; r++) {
            int idx = j + r * 256;
            int bi = idx >> 6, k2 = idx & 63;
            g_cua[(b0 + bi) * 64 + k2] =
                sp2[0][bi][k2] + sp2[1][bi][k2] + sp2[2][bi][k2] + sp2[3][bi][k2];
        }
    }
}

// ---------------- launch ----------------
extern "C" void kernel_launch(void* const* d_in, const int* in_sizes, int n_in,
                              void* d_out, int out_size)
{
    const float* H    = (const float*)d_in[0];
    const float* y0   = (const float*)d_in[1];
    const float* emb  = (const float*)d_in[2];
    const float* Wa   = (const float*)d_in[3];
    const float* Ua   = (const float*)d_in[4];
    const float* ba   = (const float*)d_in[5];
    const float* Va   = (const float*)d_in[6];
    const float* W    = (const float*)d_in[7];
    const float* U    = (const float*)d_in[8];
    const float* bias = (const float*)d_in[9];
    const float* Wy   = (const float*)d_in[10];
    const float* fcw  = (const float*)d_in[11];
    const float* fcb  = (const float*)d_in[12];

    float* outy = (float*)d_out;                 // (B, 24)
    float* outh = outy + (size_t)BB * TT;        // (B, 24, 256)

    cudaFuncSetAttribute(attn_hu, cudaFuncAttributeMaxDynamicSharedMemorySize, ATTN2_SMEM);

    convert_H<<<(BB * SEQL * IND / 4) / 256, 256>>>(H);
    convert_Wa<<<(IND * TT * TEMP / 4) / 256, 256>>>(Wa);
    init_state<<<BB, 256>>>(emb, y0, Ua);
    for (int t = 0; t < TT; t++) {
        attn_hu<<<NHU + BB * SEQL / 128, 256, ATTN2_SMEM>>>(ba, Va, U, bias, Wy, t);
        normalize_ctx<<<BB, 128>>>();
        gates_kernel<<<dim3(32, 8), 256>>>(W, t);
        update_kernel<<<64, 256>>>(fcw, fcb, Ua, t, outy, outh);
    }
}

// round 15
// speedup vs baseline: 1.2928x; 1.2928x over previous
#include <cuda_runtime.h>
#include <cuda_bf16.h>
#include <cuda_fp16.h>
#include <cstdint>

#define BB   512
#define SEQL 512
#define IND  128
#define HID  256
#define TT   24
#define TEMP 64
#define NHU  128    // hU blocks prepended to attn grid

// ---------------- persistent device scratch (no allocations) ----------------
__device__ __nv_bfloat16 g_H16[(size_t)BB * SEQL * IND];   // 67 MB
__device__ __nv_bfloat16 g_Wa16[IND * TT * TEMP];          // 384 KB
__device__ float g_h[BB * HID];
__device__ float g_c[BB * HID];
__device__ float g_y[BB];
__device__ float g_cua[BB * TEMP];
__device__ float g_ctxp[BB * 4 * IND];                     // 4 ctx partials per batch
__device__ float g_psum[BB * 4];
__device__ float g_ctx[BB * IND];
__device__ float g_hU[BB * 4 * HID];                       // h@U + bias + y*Wy
__device__ float g_gates[BB * 4 * HID];

// ---------------- asm helpers ----------------
__device__ __forceinline__ void ldsm4(uint32_t* r, uint32_t a) {
    asm volatile("ldmatrix.sync.aligned.m8n8.x4.shared.b16 {%0,%1,%2,%3}, [%4];\n"
        : "=r"(r[0]), "=r"(r[1]), "=r"(r[2]), "=r"(r[3]) : "r"(a));
}
__device__ __forceinline__ void ldsm4t(uint32_t* r, uint32_t a) {
    asm volatile("ldmatrix.sync.aligned.m8n8.x4.trans.shared.b16 {%0,%1,%2,%3}, [%4];\n"
        : "=r"(r[0]), "=r"(r[1]), "=r"(r[2]), "=r"(r[3]) : "r"(a));
}
__device__ __forceinline__ void mma_bf16(float* d, const uint32_t* a, const uint32_t* b) {
    asm volatile("mma.sync.aligned.m16n8k16.row.col.f32.bf16.bf16.f32 "
        "{%0,%1,%2,%3}, {%4,%5,%6,%7}, {%8,%9}, {%0,%1,%2,%3};\n"
        : "+f"(d[0]), "+f"(d[1]), "+f"(d[2]), "+f"(d[3])
        : "r"(a[0]), "r"(a[1]), "r"(a[2]), "r"(a[3]), "r"(b[0]), "r"(b[1]));
}
__device__ __forceinline__ void mma_tf32(float* d, const uint32_t* a, uint32_t b0, uint32_t b1) {
    asm volatile("mma.sync.aligned.m16n8k8.row.col.f32.tf32.tf32.f32 "
        "{%0,%1,%2,%3}, {%4,%5,%6,%7}, {%8,%9}, {%0,%1,%2,%3};\n"
        : "+f"(d[0]), "+f"(d[1]), "+f"(d[2]), "+f"(d[3])
        : "r"(a[0]), "r"(a[1]), "r"(a[2]), "r"(a[3]), "r"(b0), "r"(b1));
}
__device__ __forceinline__ uint32_t f2tf32(float v) {
    uint32_t u; asm("cvt.rna.tf32.f32 %0, %1;" : "=r"(u) : "f"(v)); return u;
}
__device__ __forceinline__ float2 tanh2(float x0, float x1) {
    uint32_t r;
    asm("{\n\t.reg .b32 p;\n\tcvt.rn.f16x2.f32 p, %1, %2;\n\ttanh.approx.f16x2 %0, p;\n\t}"
        : "=r"(r) : "f"(x1), "f"(x0));
    __half2 h = *reinterpret_cast<__half2*>(&r);
    return __half22float2(h);
}
__device__ __forceinline__ void cp_async16(uint32_t dst, const void* src) {
    asm volatile("cp.async.cg.shared.global [%0], [%1], 16;\n" :: "r"(dst), "l"(src));
}
__device__ __forceinline__ void cp_commit() {
    asm volatile("cp.async.commit_group;\n" ::: "memory");
}
template<int N> __device__ __forceinline__ void cp_wait() {
    asm volatile("cp.async.wait_group %0;\n" :: "n"(N) : "memory");
}
__device__ __forceinline__ uint32_t pack_bf16x2(float a, float b) {
    __nv_bfloat162 p = __floats2bfloat162_rn(a, b);
    return *(const uint32_t*)&p;
}

// ---------------- converts ----------------
__global__ void convert_H(const float* __restrict__ H) {
    int i = blockIdx.x * blockDim.x + threadIdx.x;
    float4 v = ((const float4*)H)[i];
    uint2 o;
    o.x = pack_bf16x2(v.x, v.y);
    o.y = pack_bf16x2(v.z, v.w);
    ((uint2*)g_H16)[i] = o;
}
__global__ void convert_Wa(const float* __restrict__ Wa) {
    int i = blockIdx.x * blockDim.x + threadIdx.x;
    float4 v = ((const float4*)Wa)[i];
    uint2 o;
    o.x = pack_bf16x2(v.x, v.y);
    o.y = pack_bf16x2(v.z, v.w);
    ((uint2*)g_Wa16)[i] = o;
}

// ---------------- init: state + cUa(t=0) ----------------
__global__ void init_state(const float* __restrict__ emb, const float* __restrict__ y0,
                           const float* __restrict__ Ua) {
    __shared__ float sc[256];
    __shared__ float sp[256];
    int b = blockIdx.x, j = threadIdx.x;
    float h = emb[b * 2 * HID + j];
    float c = emb[b * 2 * HID + HID + j];
    g_h[b * HID + j] = h;
    g_c[b * HID + j] = c;
    sc[j] = c;
    if (j == 0) g_y[b] = y0[b];
    __syncthreads();
    int k = j & 63, part = j >> 6;
    const float* Uc = Ua + k;
    float a = 0.f;
    int j0 = part * 64;
    #pragma unroll 8
    for (int jj = j0; jj < j0 + 64; jj++) a += sc[jj] * Uc[(size_t)jj * (TT * 64)];
    sp[part * 64 + k] = a;
    __syncthreads();
    if (j < 64) g_cua[b * 64 + j] = sp[j] + sp[64 + j] + sp[128 + j] + sp[192 + j];
}

// ---------------- merged kernel: hU blocks (0..127) + attn blocks (128..2175) ----------------
#define AH_STRIDE 136
#define AW_STRIDE 72
#define ATTN2_SMEM (128 * AH_STRIDE * 2 + IND * AW_STRIDE * 2 + 64 * 8 + 128 * 4)

__global__ __launch_bounds__(256, 4) void attn_hu(
    const float* __restrict__ ba, const float* __restrict__ Va,
    const float* __restrict__ U, const float* __restrict__ bias,
    const float* __restrict__ Wy, int t)
{
    extern __shared__ char smraw[];
    int tid = threadIdx.x, warp = tid >> 5, lane = tid & 31;

    if (blockIdx.x < NHU) {
        // ------- hU path: g_hU = h @ U_t + bias + y*Wy, tile 64b x 64n, k=256 -------
        float (*As)[64][36] = (float (*)[64][36])smraw;
        float (*Bs)[32][72] = (float (*)[32][72])(smraw + 2 * 64 * 36 * 4);
        int wm = warp & 3, wn = warp >> 2;
        int n0 = (blockIdx.x & 15) * 64, b0 = (blockIdx.x >> 4) * 64;
        float acc[4][4] = {};

        auto copy_chunk = [&](int kc, int buf) {
            #pragma unroll
            for (int i = tid; i < 512; i += 256) {
                int row = i >> 3, seg = i & 7;
                const float* src = g_h + (size_t)(b0 + row) * HID + kc * 32 + seg * 4;
                cp_async16((uint32_t)__cvta_generic_to_shared(&As[buf][row][seg * 4]), src);
            }
            #pragma unroll
            for (int i = tid; i < 512; i += 256) {
                int k = i >> 4, seg = i & 15;
                const float* src = U + (size_t)(kc * 32 + k) * (TT * 1024) + (size_t)t * 1024 + n0 + seg * 4;
                cp_async16((uint32_t)__cvta_generic_to_shared(&Bs[buf][k][seg * 4]), src);
            }
        };

        copy_chunk(0, 0); cp_commit();
        copy_chunk(1, 1); cp_commit();

        for (int kc = 0; kc < 8; kc++) {
            cp_wait<1>();
            __syncthreads();
            int buf = kc & 1;
            int ar = wm * 16 + (lane >> 2);
            int bk = lane & 3;
            int bn = wn * 32 + (lane >> 2);
            #pragma unroll
            for (int ks = 0; ks < 4; ks++) {
                uint32_t a[4];
                int ac = ks * 8 + (lane & 3);
                a[0] = f2tf32(As[buf][ar][ac]);
                a[1] = f2tf32(As[buf][ar + 8][ac]);
                a[2] = f2tf32(As[buf][ar][ac + 4]);
                a[3] = f2tf32(As[buf][ar + 8][ac + 4]);
                #pragma unroll
                for (int nt = 0; nt < 4; nt++) {
                    uint32_t b0r = f2tf32(Bs[buf][ks * 8 + bk][bn + nt * 8]);
                    uint32_t b1r = f2tf32(Bs[buf][ks * 8 + bk + 4][bn + nt * 8]);
                    mma_tf32(acc[nt], a, b0r, b1r);
                }
            }
            __syncthreads();
            if (kc + 2 < 8) copy_chunk(kc + 2, buf);
            cp_commit();
        }

        int r0 = b0 + wm * 16 + (lane >> 2);
        float y0v = g_y[r0], y1v = g_y[r0 + 8];
        #pragma unroll
        for (int nt = 0; nt < 4; nt++) {
            int n = n0 + wn * 32 + nt * 8 + (lane & 3) * 2;
            float bb0 = bias[t * 1024 + n],   bb1 = bias[t * 1024 + n + 1];
            float wy0 = Wy[t * 1024 + n],     wy1 = Wy[t * 1024 + n + 1];
            g_hU[(size_t)r0 * 1024 + n]           = acc[nt][0] + bb0 + y0v * wy0;
            g_hU[(size_t)r0 * 1024 + n + 1]       = acc[nt][1] + bb1 + y0v * wy1;
            g_hU[(size_t)(r0 + 8) * 1024 + n]     = acc[nt][2] + bb0 + y1v * wy0;
            g_hU[(size_t)(r0 + 8) * 1024 + n + 1] = acc[nt][3] + bb1 + y1v * wy1;
        }
        return;
    }

    // ------- attn path -------
    __nv_bfloat16* sA = (__nv_bfloat16*)smraw;
    __nv_bfloat16* sW = sA + 128 * AH_STRIDE;
    float* sctxp = (float*)sW;
    float2* sVC = (float2*)(smraw + 128 * AH_STRIDE * 2 + IND * AW_STRIDE * 2);
    float* se = (float*)(sVC + 64);

    int abid = blockIdx.x - NHU;
    int m0 = abid * 128;
    int b = m0 >> 9;
    int blkInB = abid & 3;
    uint32_t aBase = (uint32_t)__cvta_generic_to_shared(sA);
    uint32_t wBase = (uint32_t)__cvta_generic_to_shared(sW);

    #pragma unroll
    for (int i = tid; i < 1024; i += 256) {
        int row = i >> 3, seg = i & 7;
        cp_async16(aBase + (uint32_t)(row * AH_STRIDE + seg * 8) * 2,
                   g_H16 + (size_t)(m0 + row) * IND + seg * 8);
    }
    #pragma unroll
    for (int i = tid; i < 512; i += 256) {
        int row = i >> 3, seg = i & 7;
        cp_async16(wBase + (uint32_t)(row * AW_STRIDE + seg * 8) * 2,
                   g_Wa16 + (size_t)row * (TT * TEMP) + t * TEMP + seg * 8);
    }
    cp_commit();
    #pragma unroll
    for (int i = tid; i < 1024; i += 256) {
        int row = i >> 3, seg = (i & 7) + 8;
        cp_async16(aBase + (uint32_t)(row * AH_STRIDE + seg * 8) * 2,
                   g_H16 + (size_t)(m0 + row) * IND + seg * 8);
    }
    #pragma unroll
    for (int i = tid; i < 512; i += 256) {
        int row = (i >> 3) + 64, seg = i & 7;
        cp_async16(wBase + (uint32_t)(row * AW_STRIDE + seg * 8) * 2,
                   g_Wa16 + (size_t)row * (TT * TEMP) + t * TEMP + seg * 8);
    }
    cp_commit();

    if (tid < 64) {
        float cb = ba[t * 64 + tid] + g_cua[b * 64 + tid];
        sVC[tid] = make_float2(Va[tid * TT + t], cb);
    }

    float acc[8][4];
    #pragma unroll
    for (int ni = 0; ni < 8; ni++)
        #pragma unroll
        for (int r = 0; r < 4; r++) acc[ni][r] = 0.f;

    int lr = lane & 7, lg = (lane >> 3) & 1, lc = lane >> 4;
    int R = warp * 16;

    cp_wait<1>();
    __syncthreads();
    #pragma unroll
    for (int ks = 0; ks < 4; ks++) {
        uint32_t afr[4];
        ldsm4(afr, aBase + (uint32_t)((R + lr + lg * 8) * AH_STRIDE + ks * 16 + lc * 8) * 2);
        uint32_t bfr[4][4];
        #pragma unroll
        for (int p = 0; p < 4; p++) {
            int row = ks * 16 + lr + lg * 8;
            int col = p * 16 + lc * 8;
            ldsm4t(bfr[p], wBase + (uint32_t)(row * AW_STRIDE + col) * 2);
        }
        #pragma unroll
        for (int p = 0; p < 4; p++) {
            mma_bf16(acc[2 * p],     afr, &bfr[p][0]);
            mma_bf16(acc[2 * p + 1], afr, &bfr[p][2]);
        }
    }
    cp_wait<0>();
    __syncthreads();
    #pragma unroll
    for (int ks = 4; ks < 8; ks++) {
        uint32_t afr[4];
        ldsm4(afr, aBase + (uint32_t)((R + lr + lg * 8) * AH_STRIDE + ks * 16 + lc * 8) * 2);
        uint32_t bfr[4][4];
        #pragma unroll
        for (int p = 0; p < 4; p++) {
            int row = ks * 16 + lr + lg * 8;
            int col = p * 16 + lc * 8;
            ldsm4t(bfr[p], wBase + (uint32_t)(row * AW_STRIDE + col) * 2);
        }
        #pragma unroll
        for (int p = 0; p < 4; p++) {
            mma_bf16(acc[2 * p],     afr, &bfr[p][0]);
            mma_bf16(acc[2 * p + 1], afr, &bfr[p][2]);
        }
    }

    {
        int q = lane & 3, r = lane >> 2;
        float s0 = 0.f, s1 = 0.f;
        #pragma unroll
        for (int ni = 0; ni < 8; ni++) {
            int k0 = ni * 8 + q * 2;
            float2 vc0 = sVC[k0], vc1 = sVC[k0 + 1];
            float2 t0 = tanh2(acc[ni][0] + vc0.y, acc[ni][1] + vc1.y);
            s0 += vc0.x * t0.x + vc1.x * t0.y;
            float2 t1 = tanh2(acc[ni][2] + vc0.y, acc[ni][3] + vc1.y);
            s1 += vc0.x * t1.x + vc1.x * t1.y;
        }
        s0 += __shfl_xor_sync(0xffffffffu, s0, 1);
        s0 += __shfl_xor_sync(0xffffffffu, s0, 2);
        s1 += __shfl_xor_sync(0xffffffffu, s1, 1);
        s1 += __shfl_xor_sync(0xffffffffu, s1, 2);
        if (q == 0) {
            se[R + r]     = __expf(s0 * 0.0625f);
            se[R + r + 8] = __expf(s1 * 0.0625f);
        }
    }
    __syncthreads();

    if (tid < 32) {
        float p = se[tid] + se[tid + 32] + se[tid + 64] + se[tid + 96];
        #pragma unroll
        for (int off = 16; off; off >>= 1) p += __shfl_xor_sync(0xffffffffu, p, off);
        if (tid == 0) g_psum[b * 4 + blkInB] = p;
    }

    {
        int q = tid & 15, part = tid >> 4;
        float a[8] = {0.f, 0.f, 0.f, 0.f, 0.f, 0.f, 0.f, 0.f};
        #pragma unroll
        for (int r = 0; r < 8; r++) {
            int row = part * 8 + r;
            float pl = se[row];
            uint4 v = *(const uint4*)(sA + row * AH_STRIDE + q * 8);
            const __nv_bfloat162* h2 = (const __nv_bfloat162*)&v;
            #pragma unroll
            for (int i = 0; i < 4; i++) {
                float2 f = __bfloat1622float2(h2[i]);
                a[2 * i]     += pl * f.x;
                a[2 * i + 1] += pl * f.y;
            }
        }
        #pragma unroll
        for (int i = 0; i < 8; i++) sctxp[part * 128 + q * 8 + i] = a[i];
        __syncthreads();
        if (tid < 128) {
            float sum = 0.f;
            #pragma unroll
            for (int p = 0; p < 16; p++) sum += sctxp[p * 128 + tid];
            g_ctxp[(size_t)(b * 4 + blkInB) * IND + tid] = sum;
        }
    }
}

// ---------------- normalize: ctx = (sum of 4 ctx partials) / (sum of 4 psums) ----------------
__global__ void normalize_ctx() {
    __shared__ float sinv;
    int b = blockIdx.x, d = threadIdx.x;   // 128 threads
    if (d == 0) {
        sinv = 1.f / (g_psum[b * 4] + g_psum[b * 4 + 1] + g_psum[b * 4 + 2] + g_psum[b * 4 + 3]);
    }
    __syncthreads();
    const float* cp = g_ctxp + (size_t)b * 4 * IND;
    g_ctx[b * IND + d] = (cp[d] + cp[IND + d] + cp[2 * IND + d] + cp[3 * IND + d]) * sinv;
}

// ---------------- gates: ctx@W (k=128) + g_hU ----------------
__global__ __launch_bounds__(256) void gates_kernel(
    const float* __restrict__ W, int t)
{
    __shared__ float As[2][64][36];
    __shared__ float Bs[2][32][40];
    int tid = threadIdx.x;
    int warp = tid >> 5, lane = tid & 31;
    int wm = warp & 3, wn = warp >> 2;
    int n0 = blockIdx.x * 32, b0 = blockIdx.y * 64;
    float acc[2][4] = {};

    auto copy_chunk = [&](int kc, int buf) {
        #pragma unroll
        for (int i = tid; i < 512; i += 256) {
            int row = i >> 3, seg = i & 7;
            const float* src = g_ctx + (size_t)(b0 + row) * IND + kc * 32 + seg * 4;
            cp_async16((uint32_t)__cvta_generic_to_shared(&As[buf][row][seg * 4]), src);
        }
        {
            int k = tid >> 3, seg = tid & 7;
            const float* src = W + (size_t)(kc * 32 + k) * (TT * 1024) + (size_t)t * 1024 + n0 + seg * 4;
            cp_async16((uint32_t)__cvta_generic_to_shared(&Bs[buf][k][seg * 4]), src);
        }
    };

    copy_chunk(0, 0); cp_commit();
    copy_chunk(1, 1); cp_commit();

    for (int kc = 0; kc < 4; kc++) {
        cp_wait<1>();
        __syncthreads();
        int buf = kc & 1;
        int ar = wm * 16 + (lane >> 2);
        int bk = lane & 3;
        int bn = wn * 16 + (lane >> 2);
        #pragma unroll
        for (int ks = 0; ks < 4; ks++) {
            uint32_t a[4];
            int ac = ks * 8 + (lane & 3);
            a[0] = f2tf32(As[buf][ar][ac]);
            a[1] = f2tf32(As[buf][ar + 8][ac]);
            a[2] = f2tf32(As[buf][ar][ac + 4]);
            a[3] = f2tf32(As[buf][ar + 8][ac + 4]);
            #pragma unroll
            for (int nt = 0; nt < 2; nt++) {
                uint32_t b0r = f2tf32(Bs[buf][ks * 8 + bk][bn + nt * 8]);
                uint32_t b1r = f2tf32(Bs[buf][ks * 8 + bk + 4][bn + nt * 8]);
                mma_tf32(acc[nt], a, b0r, b1r);
            }
        }
        __syncthreads();
        if (kc + 2 < 4) copy_chunk(kc + 2, buf);
        cp_commit();
    }

    int r0 = b0 + wm * 16 + (lane >> 2);
    #pragma unroll
    for (int nt = 0; nt < 2; nt++) {
        int n = n0 + wn * 16 + nt * 8 + (lane & 3) * 2;
        g_gates[(size_t)r0 * 1024 + n]           = acc[nt][0] + g_hU[(size_t)r0 * 1024 + n];
        g_gates[(size_t)r0 * 1024 + n + 1]       = acc[nt][1] + g_hU[(size_t)r0 * 1024 + n + 1];
        g_gates[(size_t)(r0 + 8) * 1024 + n]     = acc[nt][2] + g_hU[(size_t)(r0 + 8) * 1024 + n];
        g_gates[(size_t)(r0 + 8) * 1024 + n + 1] = acc[nt][3] + g_hU[(size_t)(r0 + 8) * 1024 + n + 1];
    }
}

// ---------------- update: cell + y proj + next-step cUa (R13 version, 512 blocks) ----------------
__global__ void update_kernel(const float* __restrict__ fcw, const float* __restrict__ fcb,
                              const float* __restrict__ Ua, int t,
                              float* __restrict__ outy, float* __restrict__ outh)
{
    __shared__ float red[8];
    __shared__ float sc[256];
    __shared__ float sp[256];
    int b = blockIdx.x, j = threadIdx.x;
    size_t gi = (size_t)b * 1024;
    float i_ = 1.f / (1.f + __expf(-g_gates[gi + j]));
    float f_ = 1.f / (1.f + __expf(-g_gates[gi + 256 + j]));
    float gv = tanhf(g_gates[gi + 512 + j]);
    float o_ = 1.f / (1.f + __expf(-g_gates[gi + 768 + j]));
    float c = f_ * g_c[b * HID + j] + i_ * gv;
    float h = o_ * tanhf(c);
    g_c[b * HID + j] = c;
    g_h[b * HID + j] = h;
    sc[j] = c;
    outh[(size_t)b * TT * HID + (size_t)t * HID + j] = h;

    float p = h * fcw[t * HID + j];
    #pragma unroll
    for (int off = 16; off; off >>= 1) p += __shfl_xor_sync(0xffffffffu, p, off);
    int lane = j & 31, w = j >> 5;
    if (lane == 0) red[w] = p;
    __syncthreads();
    if (j == 0) {
        float ssum = red[0] + red[1] + red[2] + red[3] +
                     red[4] + red[5] + red[6] + red[7] + fcb[t];
        g_y[b] = ssum;
        outy[b * TT + t] = ssum;
    }

    if (t + 1 < TT) {
        int k = j & 63, part = j >> 6;
        const float* Uc = Ua + (size_t)(t + 1) * 64 + k;
        float a = 0.f;
        int j0 = part * 64;
        #pragma unroll 8
        for (int jj = j0; jj < j0 + 64; jj++) a += sc[jj] * Uc[(size_t)jj * (TT * 64)];
        sp[part * 64 + k] = a;
        __syncthreads();
        if (j < 64) g_cua[b * 64 + j] = sp[j] + sp[64 + j] + sp[128 + j] + sp[192 + j];
    }
}

// ---------------- launch ----------------
extern "C" void kernel_launch(void* const* d_in, const int* in_sizes, int n_in,
                              void* d_out, int out_size)
{
    const float* H    = (const float*)d_in[0];
    const float* y0   = (const float*)d_in[1];
    const float* emb  = (const float*)d_in[2];
    const float* Wa   = (const float*)d_in[3];
    const float* Ua   = (const float*)d_in[4];
    const float* ba   = (const float*)d_in[5];
    const float* Va   = (const float*)d_in[6];
    const float* W    = (const float*)d_in[7];
    const float* U    = (const float*)d_in[8];
    const float* bias = (const float*)d_in[9];
    const float* Wy   = (const float*)d_in[10];
    const float* fcw  = (const float*)d_in[11];
    const float* fcb  = (const float*)d_in[12];

    float* outy = (float*)d_out;                 // (B, 24)
    float* outh = outy + (size_t)BB * TT;        // (B, 24, 256)

    cudaFuncSetAttribute(attn_hu, cudaFuncAttributeMaxDynamicSharedMemorySize, ATTN2_SMEM);

    convert_H<<<(BB * SEQL * IND / 4) / 256, 256>>>(H);
    convert_Wa<<<(IND * TT * TEMP / 4) / 256, 256>>>(Wa);
    init_state<<<BB, 256>>>(emb, y0, Ua);
    for (int t = 0; t < TT; t++) {
        attn_hu<<<NHU + BB * SEQL / 128, 256, ATTN2_SMEM>>>(ba, Va, U, bias, Wy, t);
        normalize_ctx<<<BB, 128>>>();
        gates_kernel<<<dim3(32, 8), 256>>>(W, t);
        update_kernel<<<BB, 256>>>(fcw, fcb, Ua, t, outy, outh);
    }
}

// round 16
// speedup vs baseline: 1.3062x; 1.0103x over previous
#include <cuda_runtime.h>
#include <cuda_bf16.h>
#include <cuda_fp16.h>
#include <cstdint>

#define BB   512
#define SEQL 512
#define IND  128
#define HID  256
#define TT   24
#define TEMP 64
#define NHU  128    // hU blocks prepended to attn grid

// ---------------- persistent device scratch (no allocations) ----------------
__device__ __nv_bfloat16 g_H16[(size_t)BB * SEQL * IND];   // 67 MB
__device__ __nv_bfloat16 g_Wa16[IND * TT * TEMP];          // 384 KB
__device__ float g_h[BB * HID];
__device__ float g_c[BB * HID];
__device__ float g_y[BB];
__device__ float g_cua[BB * TEMP];
__device__ float g_ctxp[BB * 4 * IND];                     // 4 ctx partials per batch
__device__ float g_psum[BB * 4];
__device__ float g_ctx[BB * IND];
__device__ float g_hU[BB * 4 * HID];                       // h@U + bias + y*Wy
__device__ float g_gates[BB * 4 * HID];

// ---------------- asm helpers ----------------
__device__ __forceinline__ void ldsm4(uint32_t* r, uint32_t a) {
    asm volatile("ldmatrix.sync.aligned.m8n8.x4.shared.b16 {%0,%1,%2,%3}, [%4];\n"
        : "=r"(r[0]), "=r"(r[1]), "=r"(r[2]), "=r"(r[3]) : "r"(a));
}
__device__ __forceinline__ void ldsm4t(uint32_t* r, uint32_t a) {
    asm volatile("ldmatrix.sync.aligned.m8n8.x4.trans.shared.b16 {%0,%1,%2,%3}, [%4];\n"
        : "=r"(r[0]), "=r"(r[1]), "=r"(r[2]), "=r"(r[3]) : "r"(a));
}
__device__ __forceinline__ void mma_bf16(float* d, const uint32_t* a, const uint32_t* b) {
    asm volatile("mma.sync.aligned.m16n8k16.row.col.f32.bf16.bf16.f32 "
        "{%0,%1,%2,%3}, {%4,%5,%6,%7}, {%8,%9}, {%0,%1,%2,%3};\n"
        : "+f"(d[0]), "+f"(d[1]), "+f"(d[2]), "+f"(d[3])
        : "r"(a[0]), "r"(a[1]), "r"(a[2]), "r"(a[3]), "r"(b[0]), "r"(b[1]));
}
__device__ __forceinline__ void mma_tf32(float* d, const uint32_t* a, uint32_t b0, uint32_t b1) {
    asm volatile("mma.sync.aligned.m16n8k8.row.col.f32.tf32.tf32.f32 "
        "{%0,%1,%2,%3}, {%4,%5,%6,%7}, {%8,%9}, {%0,%1,%2,%3};\n"
        : "+f"(d[0]), "+f"(d[1]), "+f"(d[2]), "+f"(d[3])
        : "r"(a[0]), "r"(a[1]), "r"(a[2]), "r"(a[3]), "r"(b0), "r"(b1));
}
__device__ __forceinline__ uint32_t f2tf32(float v) {
    uint32_t u; asm("cvt.rna.tf32.f32 %0, %1;" : "=r"(u) : "f"(v)); return u;
}
__device__ __forceinline__ float2 tanh2(float x0, float x1) {
    uint32_t r;
    asm("{\n\t.reg .b32 p;\n\tcvt.rn.f16x2.f32 p, %1, %2;\n\ttanh.approx.f16x2 %0, p;\n\t}"
        : "=r"(r) : "f"(x1), "f"(x0));
    __half2 h = *reinterpret_cast<__half2*>(&r);
    return __half22float2(h);
}
__device__ __forceinline__ void cp_async16(uint32_t dst, const void* src) {
    asm volatile("cp.async.cg.shared.global [%0], [%1], 16;\n" :: "r"(dst), "l"(src));
}
__device__ __forceinline__ void cp_commit() {
    asm volatile("cp.async.commit_group;\n" ::: "memory");
}
template<int N> __device__ __forceinline__ void cp_wait() {
    asm volatile("cp.async.wait_group %0;\n" :: "n"(N) : "memory");
}
__device__ __forceinline__ uint32_t pack_bf16x2(float a, float b) {
    __nv_bfloat162 p = __floats2bfloat162_rn(a, b);
    return *(const uint32_t*)&p;
}

// ---------------- converts ----------------
__global__ void convert_H(const float* __restrict__ H) {
    int i = blockIdx.x * blockDim.x + threadIdx.x;
    float4 v = ((const float4*)H)[i];
    uint2 o;
    o.x = pack_bf16x2(v.x, v.y);
    o.y = pack_bf16x2(v.z, v.w);
    ((uint2*)g_H16)[i] = o;
}
__global__ void convert_Wa(const float* __restrict__ Wa) {
    int i = blockIdx.x * blockDim.x + threadIdx.x;
    float4 v = ((const float4*)Wa)[i];
    uint2 o;
    o.x = pack_bf16x2(v.x, v.y);
    o.y = pack_bf16x2(v.z, v.w);
    ((uint2*)g_Wa16)[i] = o;
}

// ---------------- init: state + cUa(t=0) ----------------
__global__ void init_state(const float* __restrict__ emb, const float* __restrict__ y0,
                           const float* __restrict__ Ua) {
    __shared__ float sc[256];
    __shared__ float sp[256];
    int b = blockIdx.x, j = threadIdx.x;
    float h = emb[b * 2 * HID + j];
    float c = emb[b * 2 * HID + HID + j];
    g_h[b * HID + j] = h;
    g_c[b * HID + j] = c;
    sc[j] = c;
    if (j == 0) g_y[b] = y0[b];
    __syncthreads();
    int k = j & 63, part = j >> 6;
    const float* Uc = Ua + k;
    float a = 0.f;
    int j0 = part * 64;
    #pragma unroll 8
    for (int jj = j0; jj < j0 + 64; jj++) a += sc[jj] * Uc[(size_t)jj * (TT * 64)];
    sp[part * 64 + k] = a;
    __syncthreads();
    if (j < 64) g_cua[b * 64 + j] = sp[j] + sp[64 + j] + sp[128 + j] + sp[192 + j];
}

// ---------------- merged kernel: hU blocks (0..127) + attn blocks (128..2175) ----------------
#define AH_STRIDE 136
#define AW_STRIDE 72
// sA 34816 | sW 18432 | sVC 512 | se 512 | se2 1024
#define SM_VC_OFF (128 * AH_STRIDE * 2 + IND * AW_STRIDE * 2)
#define ATTN2_SMEM (SM_VC_OFF + 512 + 512 + 1024)

__global__ __launch_bounds__(256, 4) void attn_hu(
    const float* __restrict__ ba, const float* __restrict__ Va,
    const float* __restrict__ U, const float* __restrict__ bias,
    const float* __restrict__ Wy, int t)
{
    extern __shared__ char smraw[];
    int tid = threadIdx.x, warp = tid >> 5, lane = tid & 31;

    if (blockIdx.x < NHU) {
        // ------- hU path: g_hU = h @ U_t + bias + y*Wy, tile 64b x 64n, k=256 -------
        float (*As)[64][36] = (float (*)[64][36])smraw;
        float (*Bs)[32][72] = (float (*)[32][72])(smraw + 2 * 64 * 36 * 4);
        int wm = warp & 3, wn = warp >> 2;
        int n0 = (blockIdx.x & 15) * 64, b0 = (blockIdx.x >> 4) * 64;
        float acc[4][4] = {};

        auto copy_chunk = [&](int kc, int buf) {
            #pragma unroll
            for (int i = tid; i < 512; i += 256) {
                int row = i >> 3, seg = i & 7;
                const float* src = g_h + (size_t)(b0 + row) * HID + kc * 32 + seg * 4;
                cp_async16((uint32_t)__cvta_generic_to_shared(&As[buf][row][seg * 4]), src);
            }
            #pragma unroll
            for (int i = tid; i < 512; i += 256) {
                int k = i >> 4, seg = i & 15;
                const float* src = U + (size_t)(kc * 32 + k) * (TT * 1024) + (size_t)t * 1024 + n0 + seg * 4;
                cp_async16((uint32_t)__cvta_generic_to_shared(&Bs[buf][k][seg * 4]), src);
            }
        };

        copy_chunk(0, 0); cp_commit();
        copy_chunk(1, 1); cp_commit();

        for (int kc = 0; kc < 8; kc++) {
            cp_wait<1>();
            __syncthreads();
            int buf = kc & 1;
            int ar = wm * 16 + (lane >> 2);
            int bk = lane & 3;
            int bn = wn * 32 + (lane >> 2);
            #pragma unroll
            for (int ks = 0; ks < 4; ks++) {
                uint32_t a[4];
                int ac = ks * 8 + (lane & 3);
                a[0] = f2tf32(As[buf][ar][ac]);
                a[1] = f2tf32(As[buf][ar + 8][ac]);
                a[2] = f2tf32(As[buf][ar][ac + 4]);
                a[3] = f2tf32(As[buf][ar + 8][ac + 4]);
                #pragma unroll
                for (int nt = 0; nt < 4; nt++) {
                    uint32_t b0r = f2tf32(Bs[buf][ks * 8 + bk][bn + nt * 8]);
                    uint32_t b1r = f2tf32(Bs[buf][ks * 8 + bk + 4][bn + nt * 8]);
                    mma_tf32(acc[nt], a, b0r, b1r);
                }
            }
            __syncthreads();
            if (kc + 2 < 8) copy_chunk(kc + 2, buf);
            cp_commit();
        }

        int r0 = b0 + wm * 16 + (lane >> 2);
        float y0v = g_y[r0], y1v = g_y[r0 + 8];
        #pragma unroll
        for (int nt = 0; nt < 4; nt++) {
            int n = n0 + wn * 32 + nt * 8 + (lane & 3) * 2;
            float bb0 = bias[t * 1024 + n],   bb1 = bias[t * 1024 + n + 1];
            float wy0 = Wy[t * 1024 + n],     wy1 = Wy[t * 1024 + n + 1];
            g_hU[(size_t)r0 * 1024 + n]           = acc[nt][0] + bb0 + y0v * wy0;
            g_hU[(size_t)r0 * 1024 + n + 1]       = acc[nt][1] + bb1 + y0v * wy1;
            g_hU[(size_t)(r0 + 8) * 1024 + n]     = acc[nt][2] + bb0 + y1v * wy0;
            g_hU[(size_t)(r0 + 8) * 1024 + n + 1] = acc[nt][3] + bb1 + y1v * wy1;
        }
        return;
    }

    // ------- attn path: warp tile 32 rows x 32 cols (4m x 2n) -------
    __nv_bfloat16* sA = (__nv_bfloat16*)smraw;
    __nv_bfloat16* sW = sA + 128 * AH_STRIDE;
    float* sctxp = (float*)sW;                                  // aliases sW after mma
    float2* sVC = (float2*)(smraw + SM_VC_OFF);
    float* se  = (float*)(sVC + 64);                            // 128
    float* se2 = se + 128;                                      // 2 x 128

    int abid = blockIdx.x - NHU;
    int m0 = abid * 128;
    int b = m0 >> 9;
    int blkInB = abid & 3;
    uint32_t aBase = (uint32_t)__cvta_generic_to_shared(sA);
    uint32_t wBase = (uint32_t)__cvta_generic_to_shared(sW);

    #pragma unroll
    for (int i = tid; i < 1024; i += 256) {
        int row = i >> 3, seg = i & 7;
        cp_async16(aBase + (uint32_t)(row * AH_STRIDE + seg * 8) * 2,
                   g_H16 + (size_t)(m0 + row) * IND + seg * 8);
    }
    #pragma unroll
    for (int i = tid; i < 512; i += 256) {
        int row = i >> 3, seg = i & 7;
        cp_async16(wBase + (uint32_t)(row * AW_STRIDE + seg * 8) * 2,
                   g_Wa16 + (size_t)row * (TT * TEMP) + t * TEMP + seg * 8);
    }
    cp_commit();
    #pragma unroll
    for (int i = tid; i < 1024; i += 256) {
        int row = i >> 3, seg = (i & 7) + 8;
        cp_async16(aBase + (uint32_t)(row * AH_STRIDE + seg * 8) * 2,
                   g_H16 + (size_t)(m0 + row) * IND + seg * 8);
    }
    #pragma unroll
    for (int i = tid; i < 512; i += 256) {
        int row = (i >> 3) + 64, seg = i & 7;
        cp_async16(wBase + (uint32_t)(row * AW_STRIDE + seg * 8) * 2,
                   g_Wa16 + (size_t)row * (TT * TEMP) + t * TEMP + seg * 8);
    }
    cp_commit();

    if (tid < 64) {
        float cb = ba[t * 64 + tid] + g_cua[b * 64 + tid];
        sVC[tid] = make_float2(Va[tid * TT + t], cb);
    }

    int wm = warp & 3, wn = warp >> 2;
    int R = wm * 32, C = wn * 32;
    float acc[2][4][4];
    #pragma unroll
    for (int mi = 0; mi < 2; mi++)
        #pragma unroll
        for (int ni = 0; ni < 4; ni++)
            #pragma unroll
            for (int r = 0; r < 4; r++) acc[mi][ni][r] = 0.f;

    int lr = lane & 7, lg = (lane >> 3) & 1, lc = lane >> 4;

    auto mma_chunk = [&](int ks) {
        uint32_t afr[2][4];
        #pragma unroll
        for (int mi = 0; mi < 2; mi++) {
            int row = R + mi * 16 + lr + lg * 8;
            ldsm4(afr[mi], aBase + (uint32_t)(row * AH_STRIDE + ks * 16 + lc * 8) * 2);
        }
        uint32_t bfr[2][4];
        #pragma unroll
        for (int p = 0; p < 2; p++) {
            int row = ks * 16 + lr + lg * 8;
            int col = C + p * 16 + lc * 8;
            ldsm4t(bfr[p], wBase + (uint32_t)(row * AW_STRIDE + col) * 2);
        }
        #pragma unroll
        for (int mi = 0; mi < 2; mi++)
            #pragma unroll
            for (int p = 0; p < 2; p++) {
                mma_bf16(acc[mi][2 * p],     afr[mi], &bfr[p][0]);
                mma_bf16(acc[mi][2 * p + 1], afr[mi], &bfr[p][2]);
            }
    };

    cp_wait<1>();
    __syncthreads();
    #pragma unroll
    for (int ks = 0; ks < 4; ks++) mma_chunk(ks);
    cp_wait<0>();
    __syncthreads();
    #pragma unroll
    for (int ks = 4; ks < 8; ks++) mma_chunk(ks);

    // partial e over this warp's 32 cols; 2 warps per row combine via se2
    {
        int q = lane & 3, r = lane >> 2;
        #pragma unroll
        for (int mi = 0; mi < 2; mi++) {
            float s0 = 0.f, s1 = 0.f;
            #pragma unroll
            for (int ni = 0; ni < 4; ni++) {
                int k0 = C + ni * 8 + q * 2;
                float2 vc0 = sVC[k0], vc1 = sVC[k0 + 1];
                float2 t0 = tanh2(acc[mi][ni][0] + vc0.y, acc[mi][ni][1] + vc1.y);
                s0 += vc0.x * t0.x + vc1.x * t0.y;
                float2 t1 = tanh2(acc[mi][ni][2] + vc0.y, acc[mi][ni][3] + vc1.y);
                s1 += vc0.x * t1.x + vc1.x * t1.y;
            }
            s0 += __shfl_xor_sync(0xffffffffu, s0, 1);
            s0 += __shfl_xor_sync(0xffffffffu, s0, 2);
            s1 += __shfl_xor_sync(0xffffffffu, s1, 1);
            s1 += __shfl_xor_sync(0xffffffffu, s1, 2);
            if (q == 0) {
                se2[wn * 128 + R + mi * 16 + r]     = s0;
                se2[wn * 128 + R + mi * 16 + r + 8] = s1;
            }
        }
    }
    __syncthreads();
    if (tid < 128) se[tid] = __expf((se2[tid] + se2[128 + tid]) * 0.0625f);
    __syncthreads();   // se complete; sW dead -> sctxp may overwrite

    if (tid < 32) {
        float p = se[tid] + se[tid + 32] + se[tid + 64] + se[tid + 96];
        #pragma unroll
        for (int off = 16; off; off >>= 1) p += __shfl_xor_sync(0xffffffffu, p, off);
        if (tid == 0) g_psum[b * 4 + blkInB] = p;
    }

    {
        int q = tid & 15, part = tid >> 4;
        float a[8] = {0.f, 0.f, 0.f, 0.f, 0.f, 0.f, 0.f, 0.f};
        #pragma unroll
        for (int r = 0; r < 8; r++) {
            int row = part * 8 + r;
            float pl = se[row];
            uint4 v = *(const uint4*)(sA + row * AH_STRIDE + q * 8);
            const __nv_bfloat162* h2 = (const __nv_bfloat162*)&v;
            #pragma unroll
            for (int i = 0; i < 4; i++) {
                float2 f = __bfloat1622float2(h2[i]);
                a[2 * i]     += pl * f.x;
                a[2 * i + 1] += pl * f.y;
            }
        }
        #pragma unroll
        for (int i = 0; i < 8; i++) sctxp[part * 128 + q * 8 + i] = a[i];
        __syncthreads();
        if (tid < 128) {
            float sum = 0.f;
            #pragma unroll
            for (int p = 0; p < 16; p++) sum += sctxp[p * 128 + tid];
            g_ctxp[(size_t)(b * 4 + blkInB) * IND + tid] = sum;
        }
    }
}

// ---------------- normalize: ctx = (sum of 4 ctx partials) / (sum of 4 psums) ----------------
__global__ void normalize_ctx() {
    __shared__ float sinv;
    int b = blockIdx.x, d = threadIdx.x;
    if (d == 0) {
        sinv = 1.f / (g_psum[b * 4] + g_psum[b * 4 + 1] + g_psum[b * 4 + 2] + g_psum[b * 4 + 3]);
    }
    __syncthreads();
    const float* cp = g_ctxp + (size_t)b * 4 * IND;
    g_ctx[b * IND + d] = (cp[d] + cp[IND + d] + cp[2 * IND + d] + cp[3 * IND + d]) * sinv;
}

// ---------------- gates: ctx@W (k=128), 64x64 tiles, grid (16,8) + g_hU ----------------
__global__ __launch_bounds__(256) void gates_kernel(
    const float* __restrict__ W, int t)
{
    __shared__ float As[2][64][36];
    __shared__ float Bs[2][32][72];
    int tid = threadIdx.x;
    int warp = tid >> 5, lane = tid & 31;
    int wm = warp & 3, wn = warp >> 2;
    int n0 = blockIdx.x * 64, b0 = blockIdx.y * 64;
    float acc[4][4] = {};

    auto copy_chunk = [&](int kc, int buf) {
        #pragma unroll
        for (int i = tid; i < 512; i += 256) {
            int row = i >> 3, seg = i & 7;
            const float* src = g_ctx + (size_t)(b0 + row) * IND + kc * 32 + seg * 4;
            cp_async16((uint32_t)__cvta_generic_to_shared(&As[buf][row][seg * 4]), src);
        }
        #pragma unroll
        for (int i = tid; i < 512; i += 256) {
            int k = i >> 4, seg = i & 15;
            const float* src = W + (size_t)(kc * 32 + k) * (TT * 1024) + (size_t)t * 1024 + n0 + seg * 4;
            cp_async16((uint32_t)__cvta_generic_to_shared(&Bs[buf][k][seg * 4]), src);
        }
    };

    copy_chunk(0, 0); cp_commit();
    copy_chunk(1, 1); cp_commit();

    for (int kc = 0; kc < 4; kc++) {
        cp_wait<1>();
        __syncthreads();
        int buf = kc & 1;
        int ar = wm * 16 + (lane >> 2);
        int bk = lane & 3;
        int bn = wn * 32 + (lane >> 2);
        #pragma unroll
        for (int ks = 0; ks < 4; ks++) {
            uint32_t a[4];
            int ac = ks * 8 + (lane & 3);
            a[0] = f2tf32(As[buf][ar][ac]);
            a[1] = f2tf32(As[buf][ar + 8][ac]);
            a[2] = f2tf32(As[buf][ar][ac + 4]);
            a[3] = f2tf32(As[buf][ar + 8][ac + 4]);
            #pragma unroll
            for (int nt = 0; nt < 4; nt++) {
                uint32_t b0r = f2tf32(Bs[buf][ks * 8 + bk][bn + nt * 8]);
                uint32_t b1r = f2tf32(Bs[buf][ks * 8 + bk + 4][bn + nt * 8]);
                mma_tf32(acc[nt], a, b0r, b1r);
            }
        }
        __syncthreads();
        if (kc + 2 < 4) copy_chunk(kc + 2, buf);
        cp_commit();
    }

    int r0 = b0 + wm * 16 + (lane >> 2);
    #pragma unroll
    for (int nt = 0; nt < 4; nt++) {
        int n = n0 + wn * 32 + nt * 8 + (lane & 3) * 2;
        g_gates[(size_t)r0 * 1024 + n]           = acc[nt][0] + g_hU[(size_t)r0 * 1024 + n];
        g_gates[(size_t)r0 * 1024 + n + 1]       = acc[nt][1] + g_hU[(size_t)r0 * 1024 + n + 1];
        g_gates[(size_t)(r0 + 8) * 1024 + n]     = acc[nt][2] + g_hU[(size_t)(r0 + 8) * 1024 + n];
        g_gates[(size_t)(r0 + 8) * 1024 + n + 1] = acc[nt][3] + g_hU[(size_t)(r0 + 8) * 1024 + n + 1];
    }
}

// ---------------- update: cell + y proj + next-step cUa ----------------
__global__ void update_kernel(const float* __restrict__ fcw, const float* __restrict__ fcb,
                              const float* __restrict__ Ua, int t,
                              float* __restrict__ outy, float* __restrict__ outh)
{
    __shared__ float red[8];
    __shared__ float sc[256];
    __shared__ float sp[256];
    int b = blockIdx.x, j = threadIdx.x;
    size_t gi = (size_t)b * 1024;
    float i_ = 1.f / (1.f + __expf(-g_gates[gi + j]));
    float f_ = 1.f / (1.f + __expf(-g_gates[gi + 256 + j]));
    float gv = tanhf(g_gates[gi + 512 + j]);
    float o_ = 1.f / (1.f + __expf(-g_gates[gi + 768 + j]));
    float c = f_ * g_c[b * HID + j] + i_ * gv;
    float h = o_ * tanhf(c);
    g_c[b * HID + j] = c;
    g_h[b * HID + j] = h;
    sc[j] = c;
    outh[(size_t)b * TT * HID + (size_t)t * HID + j] = h;

    float p = h * fcw[t * HID + j];
    #pragma unroll
    for (int off = 16; off; off >>= 1) p += __shfl_xor_sync(0xffffffffu, p, off);
    int lane = j & 31, w = j >> 5;
    if (lane == 0) red[w] = p;
    __syncthreads();
    if (j == 0) {
        float ssum = red[0] + red[1] + red[2] + red[3] +
                     red[4] + red[5] + red[6] + red[7] + fcb[t];
        g_y[b] = ssum;
        outy[b * TT + t] = ssum;
    }

    if (t + 1 < TT) {
        int k = j & 63, part = j >> 6;
        const float* Uc = Ua + (size_t)(t + 1) * 64 + k;
        float a = 0.f;
        int j0 = part * 64;
        #pragma unroll 8
        for (int jj = j0; jj < j0 + 64; jj++) a += sc[jj] * Uc[(size_t)jj * (TT * 64)];
        sp[part * 64 + k] = a;
        __syncthreads();
        if (j < 64) g_cua[b * 64 + j] = sp[j] + sp[64 + j] + sp[128 + j] + sp[192 + j];
    }
}

// ---------------- launch ----------------
extern "C" void kernel_launch(void* const* d_in, const int* in_sizes, int n_in,
                              void* d_out, int out_size)
{
    const float* H    = (const float*)d_in[0];
    const float* y0   = (const float*)d_in[1];
    const float* emb  = (const float*)d_in[2];
    const float* Wa   = (const float*)d_in[3];
    const float* Ua   = (const float*)d_in[4];
    const float* ba   = (const float*)d_in[5];
    const float* Va   = (const float*)d_in[6];
    const float* W    = (const float*)d_in[7];
    const float* U    = (const float*)d_in[8];
    const float* bias = (const float*)d_in[9];
    const float* Wy   = (const float*)d_in[10];
    const float* fcw  = (const float*)d_in[11];
    const float* fcb  = (const float*)d_in[12];

    float* outy = (float*)d_out;                 // (B, 24)
    float* outh = outy + (size_t)BB * TT;        // (B, 24, 256)

    cudaFuncSetAttribute(attn_hu, cudaFuncAttributeMaxDynamicSharedMemorySize, ATTN2_SMEM);

    convert_H<<<(BB * SEQL * IND / 4) / 256, 256>>>(H);
    convert_Wa<<<(IND * TT * TEMP / 4) / 256, 256>>>(Wa);
    init_state<<<BB, 256>>>(emb, y0, Ua);
    for (int t = 0; t < TT; t++) {
        attn_hu<<<NHU + BB * SEQL / 128, 256, ATTN2_SMEM>>>(ba, Va, U, bias, Wy, t);
        normalize_ctx<<<BB, 128>>>();
        gates_kernel<<<dim3(16, 8), 256>>>(W, t);
        update_kernel<<<BB, 256>>>(fcw, fcb, Ua, t, outy, outh);
    }
}